// round 7
// baseline (speedup 1.0000x reference)
#include <cuda_runtime.h>
#include <math.h>

// ROI max pooling, bit-exact vs JAX/XLA reference (contract proven in R2):
//   coords * 0.0625f -> __float2int_rn (round-half-even)
//   bin = roi_size * RN(1/7)   (XLA folds /7 into *recip)
//   floor/ceil edges, clip [0,50], empty bin -> 0.
//
// R7 structure:
//   K1: transpose x (B,256,2500) -> g_scr (B,2500,256)  channels-last.
//   K2: grid (M, 7), block 256 (8 warps). blockIdx.y = ph, warp = pw:
//       ONE BIN PER WARP, all 256 channels (2x float4 per lane). All cell
//       loads within a bin are independent -> latency absorbed once, not
//       per cell. Stage bin row in smem, k-linear copy to out.

static constexpr int   kC    = 256;
static constexpr int   kH    = 50;
static constexpr int   kW    = 50;
static constexpr int   kHW   = kH * kW;        // 2500
static constexpr int   kBins = 49;
static constexpr float kScale = 0.0625f;

__device__ float g_scr[4 * kHW * kC];          // 10.24 MB channels-last scratch

// ---------------- K1: NCHW -> NHWC transpose
__global__ void __launch_bounds__(256)
transpose_kernel(const float* __restrict__ x)
{
    __shared__ float tile[32][33];
    const int b   = blockIdx.z;
    const int hw0 = blockIdx.x * 32;
    const int c0  = blockIdx.y * 32;
    const int tx  = threadIdx.x;               // 32
    const int ty  = threadIdx.y;               // 8

    const float* src = x + ((size_t)b * kC + c0) * kHW + hw0;
    #pragma unroll
    for (int k = 0; k < 4; ++k) {
        if (hw0 + tx < kHW)
            tile[ty + k * 8][tx] = src[(ty + k * 8) * kHW + tx];
    }
    __syncthreads();

    float* dst = g_scr + ((size_t)b * kHW + hw0) * kC + c0;
    #pragma unroll
    for (int k = 0; k < 4; ++k) {
        if (hw0 + ty + k * 8 < kHW)
            dst[(ty + k * 8) * kC + tx] = tile[tx][ty + k * 8];
    }
}

// ---------------- K2: one bin per warp, 256 channels per warp
__global__ void __launch_bounds__(256)
roi_pool_nhwc(const float* __restrict__ rois,
              float* __restrict__ out)
{
    // staging: sout[c*7 + pw] for c in [0,256) -> the out slice this block owns
    __shared__ __align__(16) float sout[kC * 7];       // 7168 B

    const int m    = blockIdx.x;               // ROI
    const int ph   = blockIdx.y;               // 0..6
    const int t    = threadIdx.x;
    const int lane = t & 31;
    const int pw   = t >> 5;                   // warp id: bin column 0..7

    const float* r = rois + (size_t)m * 5;

    if (pw < 7) {
        // Uniform per-warp bin bounds (every lane computes the same values).
        const int b  = (int)r[0];
        const int x1 = __float2int_rn(r[1] * kScale);
        const int y1 = __float2int_rn(r[2] * kScale);
        const int x2 = __float2int_rn(r[3] * kScale);
        const int y2 = __float2int_rn(r[4] * kScale);

        const float roi_h = (float)max(y2 - y1 + 1, 1);
        const float roi_w = (float)max(x2 - x1 + 1, 1);
        const float kInv7 = 1.0f / 7.0f;       // RN(1/7), matches XLA
        const float bh = roi_h * kInv7;
        const float bw = roi_w * kInv7;

        const int hs = min(max((int)floorf((float)ph * bh)       + y1, 0), kH);
        const int he = min(max((int)ceilf((float)(ph + 1) * bh)  + y1, 0), kH);
        const int ws = min(max((int)floorf((float)pw * bw)       + x1, 0), kW);
        const int we = min(max((int)ceilf((float)(pw + 1) * bw)  + x1, 0), kW);

        // lane's two channel quads: c = 4*lane.. and c = 128+4*lane..
        const float4* __restrict__ base4 =
            (const float4*)g_scr + (size_t)b * (kHW * kC / 4) + lane;

        float v0 = -INFINITY, v1 = -INFINITY, v2 = -INFINITY, v3 = -INFINITY;
        float u0 = -INFINITY, u1 = -INFINITY, u2 = -INFINITY, u3 = -INFINITY;

        for (int h = hs; h < he; ++h) {
            const float4* __restrict__ p = base4 + (size_t)(h * kW + ws) * 64;
            for (int w = ws; w < we; ++w) {
                const float4 f = __ldg(p);          // channels 4*lane..+3
                const float4 g = __ldg(p + 32);     // channels 128+4*lane..+3
                v0 = fmaxf(v0, f.x); v1 = fmaxf(v1, f.y);
                v2 = fmaxf(v2, f.z); v3 = fmaxf(v3, f.w);
                u0 = fmaxf(u0, g.x); u1 = fmaxf(u1, g.y);
                u2 = fmaxf(u2, g.z); u3 = fmaxf(u3, g.w);
                p += 64;                            // next (h,w) cell
            }
        }

        const bool valid = (he > hs) && (we > ws);
        float* s = sout + (4 * lane) * 7 + pw;          // c-major staging
        s[0 * 7] = valid ? v0 : 0.0f;
        s[1 * 7] = valid ? v1 : 0.0f;
        s[2 * 7] = valid ? v2 : 0.0f;
        s[3 * 7] = valid ? v3 : 0.0f;
        float* s2 = s + 128 * 7;
        s2[0 * 7] = valid ? u0 : 0.0f;
        s2[1 * 7] = valid ? u1 : 0.0f;
        s2[2 * 7] = valid ? u2 : 0.0f;
        s2[3 * 7] = valid ? u3 : 0.0f;
    }
    __syncthreads();

    // Copy block's out slice: elements {c*49 + ph*7 + j : c<256, j<7}.
    float* __restrict__ obase = out + (size_t)m * (kC * kBins) + ph * 7;
    #pragma unroll
    for (int k = t; k < kC * 7; k += 256) {     // 7 iterations
        const int c = k / 7;
        const int j = k - c * 7;
        obase[c * kBins + j] = sout[k];
    }
}

extern "C" void kernel_launch(void* const* d_in, const int* in_sizes, int n_in,
                              void* d_out, int out_size)
{
    const float* x    = (const float*)d_in[0];
    const float* rois = (const float*)d_in[1];
    float*       out  = (float*)d_out;

    const int B = in_sizes[0] / (kC * kHW);
    const int M = in_sizes[1] / 5;

    dim3 tgrid((kHW + 31) / 32, kC / 32, B);   // (79, 8, B)
    transpose_kernel<<<tgrid, dim3(32, 8)>>>(x);

    dim3 pgrid(M, 7);                          // 1792 blocks, 1 bin per warp
    roi_pool_nhwc<<<pgrid, 256>>>(rois, out);
}